// round 2
// baseline (speedup 1.0000x reference)
#include <cuda_runtime.h>
#include <math.h>

// Problem shapes
#define M_TOTAL 4096     // B*S = 4*1024
#define K_DIM   1024
#define N_VOCAB 32000
#define NBITS   15

// GEMM tiling
#define BM 128
#define BN 128
#define BK 16
#define NT (N_VOCAB / BN)   // 250 column tiles

// Scratch for softmax partials (per row, per column tile)
__device__ float g_pmax[M_TOTAL * NT];
__device__ float g_psum[M_TOTAL * NT];
__device__ float g_pnum[M_TOTAL * NT * NBITS];

// ---------------------------------------------------------------------------
// Kernel 1: id_emb gather + bit_emb (+-1 bits @ weight_bit)
// grid = 4096 (one per token), block = 256 (4 dims per thread, float4)
// ---------------------------------------------------------------------------
__global__ void emb_kernel(const int* __restrict__ ids,
                           const float* __restrict__ weight,
                           const float* __restrict__ weight_bit,
                           float* __restrict__ id_emb,
                           float* __restrict__ bit_emb) {
    int bs = blockIdx.x;
    int id = ids[bs];
    id = min(max(id, 0), N_VOCAB - 1);
    int d = threadIdx.x * 4;

    float4 w = *(const float4*)(weight + (size_t)id * K_DIM + d);
    *(float4*)(id_emb + (size_t)bs * K_DIM + d) = w;

    float4 acc = make_float4(0.f, 0.f, 0.f, 0.f);
#pragma unroll
    for (int k = 0; k < NBITS; k++) {
        float s = ((id >> (NBITS - 1 - k)) & 1) ? 1.0f : -1.0f;
        float4 wb = *(const float4*)(weight_bit + k * K_DIM + d);
        acc.x += s * wb.x;
        acc.y += s * wb.y;
        acc.z += s * wb.z;
        acc.w += s * wb.w;
    }
    *(float4*)(bit_emb + (size_t)bs * K_DIM + d) = acc;
}

// ---------------------------------------------------------------------------
// Kernel 2: logit = tensor @ weight^T  (both K-major), fused softmax partials
// grid = (250, 32), block = 256; each thread computes an 8x8 microtile.
// Epilogue: per row-of-tile, compute tile max, sum(exp), and 15 bit-masked
// exp-sums; reduce across the 16 threads of a row via xor-shuffles (16-lane
// groups stay within warp halves); lane tx==0 writes partials.
// ---------------------------------------------------------------------------
__global__ __launch_bounds__(256, 2)
void gemm_kernel(const float* __restrict__ A,     // [M_TOTAL, K_DIM]
                 const float* __restrict__ W,     // [N_VOCAB, K_DIM]
                 float* __restrict__ logit) {     // [M_TOTAL, N_VOCAB]
    __shared__ float As[BK][BM];
    __shared__ float Ws[BK][BN];

    const int tid = threadIdx.x;
    const int ty = tid >> 4;        // 0..15 -> row group
    const int tx = tid & 15;        // 0..15 -> col group
    const int m0 = blockIdx.y * BM;
    const int n0 = blockIdx.x * BN;

    // load mapping: each thread loads 8 consecutive floats (2 float4) of one row
    const int loadRow = tid >> 1;          // 0..127
    const int loadCol = (tid & 1) * 8;     // 0 or 8
    const float* Ag = A + (size_t)(m0 + loadRow) * K_DIM + loadCol;
    const float* Wg = W + (size_t)(n0 + loadRow) * K_DIM + loadCol;

    float acc[8][8];
#pragma unroll
    for (int i = 0; i < 8; i++)
#pragma unroll
        for (int j = 0; j < 8; j++) acc[i][j] = 0.f;

    for (int kt = 0; kt < K_DIM; kt += BK) {
        float4 a0 = *(const float4*)(Ag + kt);
        float4 a1 = *(const float4*)(Ag + kt + 4);
        float4 w0 = *(const float4*)(Wg + kt);
        float4 w1 = *(const float4*)(Wg + kt + 4);

        __syncthreads();   // previous iteration's compute done before overwrite
        As[loadCol + 0][loadRow] = a0.x;
        As[loadCol + 1][loadRow] = a0.y;
        As[loadCol + 2][loadRow] = a0.z;
        As[loadCol + 3][loadRow] = a0.w;
        As[loadCol + 4][loadRow] = a1.x;
        As[loadCol + 5][loadRow] = a1.y;
        As[loadCol + 6][loadRow] = a1.z;
        As[loadCol + 7][loadRow] = a1.w;
        Ws[loadCol + 0][loadRow] = w0.x;
        Ws[loadCol + 1][loadRow] = w0.y;
        Ws[loadCol + 2][loadRow] = w0.z;
        Ws[loadCol + 3][loadRow] = w0.w;
        Ws[loadCol + 4][loadRow] = w1.x;
        Ws[loadCol + 5][loadRow] = w1.y;
        Ws[loadCol + 6][loadRow] = w1.z;
        Ws[loadCol + 7][loadRow] = w1.w;
        __syncthreads();

#pragma unroll
        for (int k = 0; k < BK; k++) {
            float a[8], b[8];
            float4 t0 = *(const float4*)(&As[k][ty * 8]);
            float4 t1 = *(const float4*)(&As[k][ty * 8 + 4]);
            a[0] = t0.x; a[1] = t0.y; a[2] = t0.z; a[3] = t0.w;
            a[4] = t1.x; a[5] = t1.y; a[6] = t1.z; a[7] = t1.w;
            float4 u0 = *(const float4*)(&Ws[k][tx * 8]);
            float4 u1 = *(const float4*)(&Ws[k][tx * 8 + 4]);
            b[0] = u0.x; b[1] = u0.y; b[2] = u0.z; b[3] = u0.w;
            b[4] = u1.x; b[5] = u1.y; b[6] = u1.z; b[7] = u1.w;
#pragma unroll
            for (int i = 0; i < 8; i++)
#pragma unroll
                for (int j = 0; j < 8; j++)
                    acc[i][j] += a[i] * b[j];
        }
    }

    const int gm = m0 + ty * 8;
    const int gn = n0 + tx * 8;

    // store logits (two float4 per row)
#pragma unroll
    for (int i = 0; i < 8; i++) {
        float* p = logit + (size_t)(gm + i) * N_VOCAB + gn;
        *(float4*)(p)     = make_float4(acc[i][0], acc[i][1], acc[i][2], acc[i][3]);
        *(float4*)(p + 4) = make_float4(acc[i][4], acc[i][5], acc[i][6], acc[i][7]);
    }

    // softmax partials per row of this 128-wide tile
#pragma unroll
    for (int i = 0; i < 8; i++) {
        float mx = acc[i][0];
#pragma unroll
        for (int j = 1; j < 8; j++) mx = fmaxf(mx, acc[i][j]);
#pragma unroll
        for (int o = 8; o >= 1; o >>= 1)
            mx = fmaxf(mx, __shfl_xor_sync(0xffffffffu, mx, o));

        float s = 0.f;
        float num[NBITS];
#pragma unroll
        for (int k = 0; k < NBITS; k++) num[k] = 0.f;

#pragma unroll
        for (int j = 0; j < 8; j++) {
            float e = __expf(acc[i][j] - mx);
            s += e;
            int v = gn + j;
#pragma unroll
            for (int k = 0; k < NBITS; k++) {
                if ((v >> (NBITS - 1 - k)) & 1) num[k] += e;
            }
        }
#pragma unroll
        for (int o = 8; o >= 1; o >>= 1) {
            s += __shfl_xor_sync(0xffffffffu, s, o);
#pragma unroll
            for (int k = 0; k < NBITS; k++)
                num[k] += __shfl_xor_sync(0xffffffffu, num[k], o);
        }

        if (tx == 0) {
            int idx = (gm + i) * NT + blockIdx.x;
            g_pmax[idx] = mx;
            g_psum[idx] = s;
#pragma unroll
            for (int k = 0; k < NBITS; k++)
                g_pnum[(size_t)idx * NBITS + k] = num[k];
        }
    }
}

// ---------------------------------------------------------------------------
// Kernel 3: combine 250 partials per row -> logit_w[row][15]
// grid = 4096, block = 32 (one warp per row)
// ---------------------------------------------------------------------------
__global__ void reduce_kernel(float* __restrict__ logit_w) {
    int row = blockIdx.x;
    int lane = threadIdx.x;

    float lmax = -3.402823466e38f;
    for (int t = lane; t < NT; t += 32)
        lmax = fmaxf(lmax, g_pmax[row * NT + t]);
#pragma unroll
    for (int o = 16; o >= 1; o >>= 1)
        lmax = fmaxf(lmax, __shfl_xor_sync(0xffffffffu, lmax, o));

    float tot = 0.f;
    float num[NBITS];
#pragma unroll
    for (int k = 0; k < NBITS; k++) num[k] = 0.f;

    for (int t = lane; t < NT; t += 32) {
        int idx = row * NT + t;
        float w = __expf(g_pmax[idx] - lmax);
        tot += g_psum[idx] * w;
#pragma unroll
        for (int k = 0; k < NBITS; k++)
            num[k] += g_pnum[(size_t)idx * NBITS + k] * w;
    }
#pragma unroll
    for (int o = 16; o >= 1; o >>= 1) {
        tot += __shfl_xor_sync(0xffffffffu, tot, o);
#pragma unroll
        for (int k = 0; k < NBITS; k++)
            num[k] += __shfl_xor_sync(0xffffffffu, num[k], o);
    }

    if (lane == 0) {
#pragma unroll
        for (int k = 0; k < NBITS; k++)
            logit_w[row * NBITS + k] = (2.f * num[k] - tot) / tot;
    }
}

// ---------------------------------------------------------------------------
// Launch
// inputs: [0] input_ids int32 [4,1024], [1] tensor f32 [4,1024,1024],
//         [2] weight f32 [32000,1024], [3] weight_bit f32 [15,1024]
// output: concat(id_emb, bit_emb, logit, logit_w) as f32
// ---------------------------------------------------------------------------
extern "C" void kernel_launch(void* const* d_in, const int* in_sizes, int n_in,
                              void* d_out, int out_size) {
    const int*   ids        = (const int*)d_in[0];
    const float* tensor     = (const float*)d_in[1];
    const float* weight     = (const float*)d_in[2];
    const float* weight_bit = (const float*)d_in[3];

    float* out     = (float*)d_out;
    float* id_emb  = out;                                   // 4*1024*1024
    float* bit_emb = out + 4194304;                         // 4*1024*1024
    float* logit   = out + 8388608;                         // 4*1024*32000
    float* logit_w = out + 8388608 + 131072000;             // 4*1024*15

    emb_kernel<<<M_TOTAL, 256>>>(ids, weight, weight_bit, id_emb, bit_emb);
    gemm_kernel<<<dim3(NT, M_TOTAL / BM), 256>>>(tensor, weight, logit);
    reduce_kernel<<<M_TOTAL, 32>>>(logit_w);
}

// round 4
// speedup vs baseline: 3.2621x; 3.2621x over previous
#include <cuda_runtime.h>
#include <cuda_bf16.h>
#include <math.h>
#include <stdint.h>

// ---------------------------------------------------------------- shapes
#define M_TOTAL 4096
#define K_DIM   1024
#define N_VOCAB 32000
#define NBITS   15
#define KP      3072            // K' = 3*K (bf16 split-3 concatenated)
#define BM      128
#define BN      128
#define BK      64
#define NKI     48              // KP / BK
#define NT2     1000            // 32-wide partial tiles per row

#define STAGE   32768           // 16KB A + 16KB B
#define NSTAGE  3
#define DSMEM   (NSTAGE * STAGE + 128)

// ---------------------------------------------------------------- scratch
__device__ __nv_bfloat16 g_A2[(size_t)M_TOTAL * KP];   // [Ah | Ah | Al]
__device__ __nv_bfloat16 g_B2[(size_t)N_VOCAB * KP];   // [Bh | Bl | Bh]
__device__ float g_pmax[M_TOTAL * NT2];
__device__ float g_psum[M_TOTAL * NT2];
__device__ float g_pnum[(size_t)M_TOTAL * NT2 * 5];    // low-5-bit masked sums

// ---------------------------------------------------------------- helpers
__device__ __forceinline__ uint32_t smem_u32(const void* p) {
    uint32_t a;
    asm("{ .reg .u64 t; cvta.to.shared.u64 t, %1; cvt.u32.u64 %0, t; }" : "=r"(a) : "l"(p));
    return a;
}
__device__ __forceinline__ void cp_async16(uint32_t dst, const void* src) {
    asm volatile("cp.async.cg.shared.global [%0], [%1], 16;" :: "r"(dst), "l"(src) : "memory");
}
__device__ __forceinline__ void cp_commit() {
    asm volatile("cp.async.commit_group;" ::: "memory");
}
template <int N>
__device__ __forceinline__ void cp_wait() {
    asm volatile("cp.async.wait_group %0;" :: "n"(N) : "memory");
}
__device__ __forceinline__ void ldsm_x4(uint32_t* r, uint32_t addr) {
    asm volatile("ldmatrix.sync.aligned.m8n8.x4.shared.b16 {%0,%1,%2,%3}, [%4];"
                 : "=r"(r[0]), "=r"(r[1]), "=r"(r[2]), "=r"(r[3]) : "r"(addr));
}
__device__ __forceinline__ void mma_bf16(float* c, const uint32_t* a, const uint32_t* b) {
    asm volatile("mma.sync.aligned.m16n8k16.row.col.f32.bf16.bf16.f32 "
                 "{%0,%1,%2,%3}, {%4,%5,%6,%7}, {%8,%9}, {%0,%1,%2,%3};"
                 : "+f"(c[0]), "+f"(c[1]), "+f"(c[2]), "+f"(c[3])
                 : "r"(a[0]), "r"(a[1]), "r"(a[2]), "r"(a[3]), "r"(b[0]), "r"(b[1]));
}
#define SWZ(off) ((off) ^ (((off) >> 3) & 0x70))

// ---------------------------------------------------------------- converters
__device__ __forceinline__ uint32_t pack_bf2(__nv_bfloat16 lo, __nv_bfloat16 hi) {
    return (uint32_t)__bfloat16_as_ushort(lo) | ((uint32_t)__bfloat16_as_ushort(hi) << 16);
}

__global__ void convertW_kernel(const float* __restrict__ W) {
    size_t i = ((size_t)blockIdx.x * 256 + threadIdx.x) * 4;
    int row = (int)(i >> 10);
    int col = (int)(i & 1023);
    float4 w = *(const float4*)(W + i);
    __nv_bfloat16 h0 = __float2bfloat16_rn(w.x), h1 = __float2bfloat16_rn(w.y);
    __nv_bfloat16 h2 = __float2bfloat16_rn(w.z), h3 = __float2bfloat16_rn(w.w);
    __nv_bfloat16 l0 = __float2bfloat16_rn(w.x - __bfloat162float(h0));
    __nv_bfloat16 l1 = __float2bfloat16_rn(w.y - __bfloat162float(h1));
    __nv_bfloat16 l2 = __float2bfloat16_rn(w.z - __bfloat162float(h2));
    __nv_bfloat16 l3 = __float2bfloat16_rn(w.w - __bfloat162float(h3));
    uint2 hi = make_uint2(pack_bf2(h0, h1), pack_bf2(h2, h3));
    uint2 lo = make_uint2(pack_bf2(l0, l1), pack_bf2(l2, l3));
    char* base = (char*)g_B2 + ((size_t)row * KP) * 2;
    *(uint2*)(base + (size_t)(col) * 2)        = hi;  // Bh
    *(uint2*)(base + (size_t)(1024 + col) * 2) = lo;  // Bl
    *(uint2*)(base + (size_t)(2048 + col) * 2) = hi;  // Bh
}

__global__ void convertA_kernel(const float* __restrict__ A) {
    size_t i = ((size_t)blockIdx.x * 256 + threadIdx.x) * 4;
    int row = (int)(i >> 10);
    int col = (int)(i & 1023);
    float4 w = *(const float4*)(A + i);
    __nv_bfloat16 h0 = __float2bfloat16_rn(w.x), h1 = __float2bfloat16_rn(w.y);
    __nv_bfloat16 h2 = __float2bfloat16_rn(w.z), h3 = __float2bfloat16_rn(w.w);
    __nv_bfloat16 l0 = __float2bfloat16_rn(w.x - __bfloat162float(h0));
    __nv_bfloat16 l1 = __float2bfloat16_rn(w.y - __bfloat162float(h1));
    __nv_bfloat16 l2 = __float2bfloat16_rn(w.z - __bfloat162float(h2));
    __nv_bfloat16 l3 = __float2bfloat16_rn(w.w - __bfloat162float(h3));
    uint2 hi = make_uint2(pack_bf2(h0, h1), pack_bf2(h2, h3));
    uint2 lo = make_uint2(pack_bf2(l0, l1), pack_bf2(l2, l3));
    char* base = (char*)g_A2 + ((size_t)row * KP) * 2;
    *(uint2*)(base + (size_t)(col) * 2)        = hi;  // Ah
    *(uint2*)(base + (size_t)(1024 + col) * 2) = hi;  // Ah
    *(uint2*)(base + (size_t)(2048 + col) * 2) = lo;  // Al
}

// ---------------------------------------------------------------- emb kernel
__global__ void emb_kernel(const int* __restrict__ ids,
                           const float* __restrict__ weight,
                           const float* __restrict__ weight_bit,
                           float* __restrict__ id_emb,
                           float* __restrict__ bit_emb) {
    int bs = blockIdx.x;
    int id = ids[bs];
    id = min(max(id, 0), N_VOCAB - 1);
    int d = threadIdx.x * 4;

    float4 w = *(const float4*)(weight + (size_t)id * K_DIM + d);
    *(float4*)(id_emb + (size_t)bs * K_DIM + d) = w;

    float4 acc = make_float4(0.f, 0.f, 0.f, 0.f);
#pragma unroll
    for (int k = 0; k < NBITS; k++) {
        float s = ((id >> (NBITS - 1 - k)) & 1) ? 1.0f : -1.0f;
        float4 wb = *(const float4*)(weight_bit + k * K_DIM + d);
        acc.x += s * wb.x; acc.y += s * wb.y; acc.z += s * wb.z; acc.w += s * wb.w;
    }
    *(float4*)(bit_emb + (size_t)bs * K_DIM + d) = acc;
}

// ---------------------------------------------------------------- GEMM (mma.sync)
__device__ __forceinline__ void load_stage(uint32_t sA, int m0, int n0, int kb, int tid) {
    uint32_t sB = sA + 16384;
#pragma unroll
    for (int u = 0; u < 4; ++u) {
        int seg = tid + u * 256;
        int row = seg >> 3, c = seg & 7;
        uint32_t off = row * 128 + c * 16;
        cp_async16(sA + SWZ(off),
                   (const char*)g_A2 + ((size_t)(m0 + row) * KP + kb * 64 + c * 8) * 2);
    }
#pragma unroll
    for (int u = 0; u < 4; ++u) {
        int seg = tid + u * 256;
        int row = seg >> 3, c = seg & 7;
        uint32_t off = row * 128 + c * 16;
        cp_async16(sB + SWZ(off),
                   (const char*)g_B2 + ((size_t)(n0 + row) * KP + kb * 64 + c * 8) * 2);
    }
}

__global__ void __launch_bounds__(256, 2)
gemm_mma_kernel(float* __restrict__ logit) {
    extern __shared__ char dynsmem[];
    const int tid = threadIdx.x;
    const int lane = tid & 31;
    const int wid = tid >> 5;
    const int warp_m = wid >> 2;        // 0..1  (64 rows each)
    const int warp_n = wid & 3;         // 0..3  (32 cols each)
    const int m0 = blockIdx.x * BM;     // m fastest -> B reuse in L2
    const int n0 = blockIdx.y * BN;

    uint32_t tile0 = (smem_u32(dynsmem) + 127) & ~127u;

    // ldmatrix per-lane addressing components
    const int a_row   = warp_m * 64 + (lane & 15);
    const int a_chunk = lane >> 4;                          // 0/1 -> k8 half
    const int bg      = lane >> 3;                          // 0..3
    const int b_row   = warp_n * 32 + ((bg >> 1) << 3) + (lane & 7);
    const int b_chunk = bg & 1;

    float acc[4][4][4];
#pragma unroll
    for (int i = 0; i < 4; i++)
#pragma unroll
        for (int j = 0; j < 4; j++)
#pragma unroll
            for (int q = 0; q < 4; q++) acc[i][j][q] = 0.f;

    // prologue: stages 0,1
    load_stage(tile0 + 0 * STAGE, m0, n0, 0, tid); cp_commit();
    load_stage(tile0 + 1 * STAGE, m0, n0, 1, tid); cp_commit();

#pragma unroll 1
    for (int kt = 0; kt < NKI; ++kt) {
        cp_wait<1>();
        __syncthreads();

        int kn = kt + 2;
        if (kn < NKI) load_stage(tile0 + (kn % NSTAGE) * STAGE, m0, n0, kn, tid);
        cp_commit();

        uint32_t sA = tile0 + (kt % NSTAGE) * STAGE;
        uint32_t sB = sA + 16384;

#pragma unroll
        for (int ks = 0; ks < 4; ++ks) {
            uint32_t af[4][4];
            uint32_t bf[2][4];
#pragma unroll
            for (int i = 0; i < 4; ++i) {
                uint32_t off = (uint32_t)(a_row + i * 16) * 128 + (ks * 2 + a_chunk) * 16;
                ldsm_x4(af[i], sA + SWZ(off));
            }
#pragma unroll
            for (int j = 0; j < 2; ++j) {
                uint32_t off = (uint32_t)(b_row + j * 16) * 128 + (ks * 2 + b_chunk) * 16;
                ldsm_x4(bf[j], sB + SWZ(off));
            }
#pragma unroll
            for (int i = 0; i < 4; ++i)
#pragma unroll
                for (int jj = 0; jj < 4; ++jj)
                    mma_bf16(acc[i][jj], af[i], &bf[jj >> 1][(jj & 1) * 2]);
        }
    }

    // ---------------- epilogue: store logits + fused softmax partials
    const int n_base = n0 + warp_n * 32;
    const int t32 = n_base >> 5;

#pragma unroll
    for (int i = 0; i < 4; ++i) {
#pragma unroll
        for (int half = 0; half < 2; ++half) {
            const int gm = m0 + warp_m * 64 + i * 16 + (lane >> 2) + half * 8;
            float v[8];
#pragma unroll
            for (int j = 0; j < 4; ++j) {
                v[2 * j]     = acc[i][j][half * 2];
                v[2 * j + 1] = acc[i][j][half * 2 + 1];
            }
            float* p = logit + (size_t)gm * N_VOCAB + n_base;
#pragma unroll
            for (int j = 0; j < 4; ++j)
                *(float2*)(p + j * 8 + (lane & 3) * 2) = make_float2(v[2 * j], v[2 * j + 1]);

            float mx = v[0];
#pragma unroll
            for (int q = 1; q < 8; ++q) mx = fmaxf(mx, v[q]);
            mx = fmaxf(mx, __shfl_xor_sync(0xffffffffu, mx, 1));
            mx = fmaxf(mx, __shfl_xor_sync(0xffffffffu, mx, 2));

            float S = 0.f, b0 = 0.f, b3 = 0.f, b4 = 0.f;
#pragma unroll
            for (int j = 0; j < 4; ++j) {
                float e0 = __expf(v[2 * j] - mx);
                float e1 = __expf(v[2 * j + 1] - mx);
                float s2 = e0 + e1;
                S += s2;
                b0 += e1;                  // col bit0 = odd element
                if (j & 1) b3 += s2;       // col bit3 = j&1
                if (j & 2) b4 += s2;       // col bit4 = j&2
            }
            float b1 = (lane & 1) ? S : 0.f;   // col bit1 = lane&1
            float b2 = (lane & 2) ? S : 0.f;   // col bit2 = lane&2

#pragma unroll
            for (int o = 1; o <= 2; o <<= 1) {
                S  += __shfl_xor_sync(0xffffffffu, S, o);
                b0 += __shfl_xor_sync(0xffffffffu, b0, o);
                b1 += __shfl_xor_sync(0xffffffffu, b1, o);
                b2 += __shfl_xor_sync(0xffffffffu, b2, o);
                b3 += __shfl_xor_sync(0xffffffffu, b3, o);
                b4 += __shfl_xor_sync(0xffffffffu, b4, o);
            }

            if ((lane & 3) == 0) {
                int idx = gm * NT2 + t32;
                g_pmax[idx] = mx;
                g_psum[idx] = S;
                float* pn = g_pnum + (size_t)idx * 5;
                pn[0] = b4;   // logit_w k=10 (bit 4)
                pn[1] = b3;   // k=11
                pn[2] = b2;   // k=12
                pn[3] = b1;   // k=13
                pn[4] = b0;   // k=14 (bit 0)
            }
        }
    }
}

// ---------------------------------------------------------------- reduce
__global__ void reduce_kernel(float* __restrict__ logit_w) {
    int row = blockIdx.x;
    int lane = threadIdx.x;

    float lmax = -3.402823466e38f;
    for (int t = lane; t < NT2; t += 32)
        lmax = fmaxf(lmax, g_pmax[row * NT2 + t]);
#pragma unroll
    for (int o = 16; o >= 1; o >>= 1)
        lmax = fmaxf(lmax, __shfl_xor_sync(0xffffffffu, lmax, o));

    float tot = 0.f;
    float num[NBITS];
#pragma unroll
    for (int k = 0; k < NBITS; k++) num[k] = 0.f;

    for (int t = lane; t < NT2; t += 32) {
        int idx = row * NT2 + t;
        float w = __expf(g_pmax[idx] - lmax);
        float Sw = g_psum[idx] * w;
        tot += Sw;
        int vb = t << 5;                       // tile's vocab base (high 10 bits constant)
#pragma unroll
        for (int k = 0; k < 10; k++)
            if ((vb >> (14 - k)) & 1) num[k] += Sw;
        const float* pn = g_pnum + (size_t)idx * 5;
        num[10] += pn[0] * w;
        num[11] += pn[1] * w;
        num[12] += pn[2] * w;
        num[13] += pn[3] * w;
        num[14] += pn[4] * w;
    }
#pragma unroll
    for (int o = 16; o >= 1; o >>= 1) {
        tot += __shfl_xor_sync(0xffffffffu, tot, o);
#pragma unroll
        for (int k = 0; k < NBITS; k++)
            num[k] += __shfl_xor_sync(0xffffffffu, num[k], o);
    }

    if (lane == 0) {
#pragma unroll
        for (int k = 0; k < NBITS; k++)
            logit_w[row * NBITS + k] = (2.f * num[k] - tot) / tot;
    }
}

// ---------------------------------------------------------------- launch
extern "C" void kernel_launch(void* const* d_in, const int* in_sizes, int n_in,
                              void* d_out, int out_size) {
    const int*   ids        = (const int*)d_in[0];
    const float* tensor     = (const float*)d_in[1];
    const float* weight     = (const float*)d_in[2];
    const float* weight_bit = (const float*)d_in[3];

    float* out     = (float*)d_out;
    float* id_emb  = out;
    float* bit_emb = out + 4194304;
    float* logit   = out + 8388608;
    float* logit_w = out + 8388608 + 131072000;

    cudaFuncSetAttribute(gemm_mma_kernel, cudaFuncAttributeMaxDynamicSharedMemorySize, DSMEM);

    convertA_kernel<<<4096, 256>>>(tensor);
    convertW_kernel<<<32000, 256>>>(weight);
    emb_kernel<<<M_TOTAL, 256>>>(ids, weight, weight_bit, id_emb, bit_emb);
    gemm_mma_kernel<<<dim3(M_TOTAL / BM, N_VOCAB / BN), 256, DSMEM>>>(logit);
    reduce_kernel<<<M_TOTAL, 32>>>(logit_w);
}